// round 5
// baseline (speedup 1.0000x reference)
#include <cuda_runtime.h>
#include <cuda_fp16.h>
#include <cstdint>

// ---------------- problem constants ----------------
#define HID        256
#define OBS_STRIDE 54
#define SELF_OBS   18
#define NBR        6
#define BATCH_N    131072
#define TILE_B     16                    // batches per CTA iteration
#define NTILES     (BATCH_N / TILE_B)    // 8192
#define THREADS    256                   // 8 warps: warp h owns hidden cols [32h, 32h+32)
#define GRID_X     152

// ==================== helpers ====================
static __device__ __forceinline__ float tanha(float x) {
    float y;
    asm("tanh.approx.f32 %0, %1;" : "=f"(y) : "f"(x));
    return y;
}
static __device__ __forceinline__ uint32_t packh2(float a, float b) {
    __half2 h = __floats2half2_rn(a, b);
    return *reinterpret_cast<uint32_t*>(&h);
}
// D[16x8] += A[16x8] * B[8x8]   (f16 in, f32 accum)
static __device__ __forceinline__ void mma_k8(float& d0, float& d1, float& d2, float& d3,
                                              uint32_t a0, uint32_t a1, uint32_t b0) {
    asm volatile("mma.sync.aligned.m16n8k8.row.col.f32.f16.f16.f32 "
                 "{%0,%1,%2,%3}, {%4,%5}, {%6}, {%0,%1,%2,%3};"
                 : "+f"(d0), "+f"(d1), "+f"(d2), "+f"(d3)
                 : "r"(a0), "r"(a1), "r"(b0));
}
// D[16x8] += A[16x16] * B[16x8]
static __device__ __forceinline__ void mma_k16(float* d,
                                               uint32_t a0, uint32_t a1, uint32_t a2, uint32_t a3,
                                               uint32_t b0, uint32_t b1) {
    asm volatile("mma.sync.aligned.m16n8k16.row.col.f32.f16.f16.f32 "
                 "{%0,%1,%2,%3}, {%4,%5,%6,%7}, {%8,%9}, {%0,%1,%2,%3};"
                 : "+f"(d[0]), "+f"(d[1]), "+f"(d[2]), "+f"(d[3])
                 : "r"(a0), "r"(a1), "r"(a2), "r"(a3), "r"(b0), "r"(b1));
}

// ==================== kernel ====================
__global__ void __launch_bounds__(THREADS, 1)
deepsets_kernel(const float* __restrict__ obs,
                const float* __restrict__ W1,
                const float* __restrict__ b1,
                const float* __restrict__ W2,
                const float* __restrict__ b2,
                float* __restrict__ out)
{
    // x staging: [neighbor][row(batch)][k] fp16, k padded 6->8
    __shared__ __half xs[NBR][TILE_B][8];
    // W1 transposed: [n][k8] fp16
    __shared__ __half w1t[HID][8];
    // A-fragment exchange, double buffered: [buf][k-chunk][lane] 16B
    __shared__ uint4 exch[2][16][32];

    const int tid  = threadIdx.x;
    const int h    = tid >> 5;      // warp id = hidden n-slice
    const int lane = tid & 31;
    const int gid  = lane >> 2;     // fragment row group (0..7)
    const int tig  = lane & 3;      // thread-in-group
    const int n0   = h * 32;

    // ---- stage W1^T into smem (zero-pad k=6,7) ----
    for (int i = tid; i < HID * 8; i += THREADS) {
        int n = i >> 3, k = i & 7;
        w1t[n][k] = (k < 6) ? __float2half(W1[k * HID + n]) : __float2half(0.0f);
    }

    // ---- per-thread bias fragments ----
    float2 b1v[4], b2v[4];
    #pragma unroll
    for (int j = 0; j < 4; j++) {
        int c1 = (h * 4 + j) * 8 + 2 * tig;       // layer-1 tile cols (this warp's hidden range)
        b1v[j] = make_float2(b1[c1], b1[c1 + 1]);
        int c2 = n0 + j * 8 + 2 * tig;            // layer-2 output cols
        b2v[j] = make_float2(b2[c2], b2[c2 + 1]);
    }

    // ---- resident W2 B-fragments: warp h holds W2[:, n0..n0+31] ----
    uint32_t blo[16][4], bhi[16][4];
    #pragma unroll
    for (int c = 0; c < 16; c++) {
        #pragma unroll
        for (int t = 0; t < 4; t++) {
            int n = n0 + t * 8 + gid;
            int k = c * 16 + 2 * tig;
            blo[c][t] = packh2(W2[k * HID + n],       W2[(k + 1) * HID + n]);
            bhi[c][t] = packh2(W2[(k + 8) * HID + n], W2[(k + 9) * HID + n]);
        }
    }
    __syncthreads();   // w1t ready

    const float inv6 = 1.0f / 6.0f;

    // layer-1 for one neighbor -> packed A fragments (pk0, pk1)
    auto layer1 = [&](int nb, uint4& pk0, uint4& pk1) {
        uint32_t xa0 = *reinterpret_cast<const uint32_t*>(&xs[nb][gid][2 * tig]);
        uint32_t xa1 = *reinterpret_cast<const uint32_t*>(&xs[nb][gid + 8][2 * tig]);
        uint32_t* pk = reinterpret_cast<uint32_t*>(&pk0);
        #pragma unroll
        for (int j = 0; j < 4; j++) {
            if (j == 2) pk = reinterpret_cast<uint32_t*>(&pk1);
            int tt = h * 4 + j;            // global hidden n8-tile
            uint32_t bb = *reinterpret_cast<const uint32_t*>(&w1t[tt * 8 + gid][2 * tig]);
            float d0 = 0.f, d1 = 0.f, d2 = 0.f, d3 = 0.f;
            mma_k8(d0, d1, d2, d3, xa0, xa1, bb);
            d0 += b1v[j].x; d1 += b1v[j].y;
            d2 += b1v[j].x; d3 += b1v[j].y;
            pk[(j & 1) * 2 + 0] = packh2(tanha(d0), tanha(d1));
            pk[(j & 1) * 2 + 1] = packh2(tanha(d2), tanha(d3));
        }
    };

    for (int tile = blockIdx.x; tile < NTILES; tile += gridDim.x) {
        // ---- stage x (neighbor obs) for 16 batches ----
        for (int i = tid; i < NBR * TILE_B * 6; i += THREADS) {
            int k  = i % 6;
            int r  = (i / 6) % TILE_B;
            int nb = i / (6 * TILE_B);
            long b = (long)tile * TILE_B + r;
            xs[nb][r][k] = __float2half(obs[b * OBS_STRIDE + SELF_OBS + nb * 6 + k]);
        }
        if (tid < NBR * TILE_B) {   // zero pad k = 6,7
            *reinterpret_cast<uint32_t*>(&xs[tid / TILE_B][tid % TILE_B][6]) = 0u;
        }
        __syncthreads();           // xs ready (also: exch[0] reads of prev tile done)

        float acc[4][4];
        #pragma unroll
        for (int t = 0; t < 4; t++)
            #pragma unroll
            for (int i = 0; i < 4; i++) acc[t][i] = 0.0f;

        // ---- prologue: A(0) into exch[0] ----
        {
            uint4 pk0, pk1;
            layer1(0, pk0, pk1);
            exch[0][2 * h + 0][lane] = pk0;
            exch[0][2 * h + 1][lane] = pk1;
        }
        __syncthreads();

        // ---- pipelined neighbor loop: layer1(nb+1) overlaps MMA(nb)+epilogue ----
        #pragma unroll 2
        for (int nb = 0; nb < NBR; nb++) {
            const int buf = nb & 1;

            // produce A(nb+1) into the other buffer (MUFU/FMA stream)
            if (nb < NBR - 1) {
                uint4 pk0, pk1;
                layer1(nb + 1, pk0, pk1);
                exch[buf ^ 1][2 * h + 0][lane] = pk0;
                exch[buf ^ 1][2 * h + 1][lane] = pk1;
            }

            // consume A(nb): D[16 x 32] = h1[16 x 256] @ W2[:, n0..n0+31] (tensor stream)
            float D[4][4];
            #pragma unroll
            for (int t = 0; t < 4; t++)
                #pragma unroll
                for (int i = 0; i < 4; i++) D[t][i] = 0.0f;

            #pragma unroll
            for (int c = 0; c < 16; c++) {
                uint4 a = exch[buf][c][lane];
                #pragma unroll
                for (int t = 0; t < 4; t++)
                    mma_k16(D[t], a.x, a.y, a.z, a.w, blo[c][t], bhi[c][t]);
            }

            // epilogue: acc += tanh(D + b2)
            #pragma unroll
            for (int t = 0; t < 4; t++) {
                acc[t][0] += tanha(D[t][0] + b2v[t].x);
                acc[t][1] += tanha(D[t][1] + b2v[t].y);
                acc[t][2] += tanha(D[t][2] + b2v[t].x);
                acc[t][3] += tanha(D[t][3] + b2v[t].y);
            }

            __syncthreads();  // write(nb+1) visible before read(nb+1); read(nb) done before write(nb+2)
        }

        // ---- mean over neighbors, write out ----
        long b = (long)tile * TILE_B;
        #pragma unroll
        for (int t = 0; t < 4; t++) {
            int col = n0 + t * 8 + 2 * tig;
            float2 v0 = make_float2(acc[t][0] * inv6, acc[t][1] * inv6);
            float2 v1 = make_float2(acc[t][2] * inv6, acc[t][3] * inv6);
            *reinterpret_cast<float2*>(&out[(b + gid)     * HID + col]) = v0;
            *reinterpret_cast<float2*>(&out[(b + gid + 8) * HID + col]) = v1;
        }
        // NOTE: no extra barrier needed here; the loop's final __syncthreads()
        // already separates the last exch/xs reads from next tile's staging writes.
    }
}

// ==================== launch ====================
extern "C" void kernel_launch(void* const* d_in, const int* in_sizes, int n_in,
                              void* d_out, int out_size) {
    // inputs: self_obs(131072*18), obs(131072*54), W1(6*256), b1(256), W2(256*256), b2(256)
    const float* obs = nullptr;
    const float* W1  = nullptr;
    const float* b1  = nullptr;
    const float* W2  = nullptr;
    const float* b2  = nullptr;
    for (int i = 0; i < n_in; i++) {
        int sz = in_sizes[i];
        if (sz == BATCH_N * OBS_STRIDE)  obs = (const float*)d_in[i];
        else if (sz == 6 * HID)          W1  = (const float*)d_in[i];
        else if (sz == HID * HID)        W2  = (const float*)d_in[i];
        else if (sz == HID) {
            if (!b1) b1 = (const float*)d_in[i];
            else if (!b2) b2 = (const float*)d_in[i];
        }
    }
    float* out = (float*)d_out;
    deepsets_kernel<<<GRID_X, THREADS>>>(obs, W1, b1, W2, b2, out);
}

// round 6
// speedup vs baseline: 1.0803x; 1.0803x over previous
#include <cuda_runtime.h>
#include <cuda_fp16.h>
#include <cstdint>

// ---------------- problem constants ----------------
#define HID        256
#define OBS_STRIDE 54
#define SELF_OBS   18
#define NBR        6
#define BATCH_N    131072
#define TILE_B     16                    // batches per CTA iteration
#define NTILES     (BATCH_N / TILE_B)    // 8192
#define THREADS    512                   // 16 warps: warp w owns hidden/output cols [16w, 16w+16)
#define GRID_X     152

// ==================== helpers ====================
static __device__ __forceinline__ float tanha(float x) {
    float y;
    asm("tanh.approx.f32 %0, %1;" : "=f"(y) : "f"(x));
    return y;
}
static __device__ __forceinline__ uint32_t packh2(float a, float b) {
    __half2 h = __floats2half2_rn(a, b);
    return *reinterpret_cast<uint32_t*>(&h);
}
// D[16x8] += A[16x8] * B[8x8]   (f16 in, f32 accum)
static __device__ __forceinline__ void mma_k8(float& d0, float& d1, float& d2, float& d3,
                                              uint32_t a0, uint32_t a1, uint32_t b0) {
    asm volatile("mma.sync.aligned.m16n8k8.row.col.f32.f16.f16.f32 "
                 "{%0,%1,%2,%3}, {%4,%5}, {%6}, {%0,%1,%2,%3};"
                 : "+f"(d0), "+f"(d1), "+f"(d2), "+f"(d3)
                 : "r"(a0), "r"(a1), "r"(b0));
}
// D[16x8] += A[16x16] * B[16x8]
static __device__ __forceinline__ void mma_k16(float* d,
                                               uint32_t a0, uint32_t a1, uint32_t a2, uint32_t a3,
                                               uint32_t b0, uint32_t b1) {
    asm volatile("mma.sync.aligned.m16n8k16.row.col.f32.f16.f16.f32 "
                 "{%0,%1,%2,%3}, {%4,%5,%6,%7}, {%8,%9}, {%0,%1,%2,%3};"
                 : "+f"(d[0]), "+f"(d[1]), "+f"(d[2]), "+f"(d[3])
                 : "r"(a0), "r"(a1), "r"(a2), "r"(a3), "r"(b0), "r"(b1));
}

// ==================== kernel ====================
__global__ void __launch_bounds__(THREADS, 1)
deepsets_kernel(const float* __restrict__ obs,
                const float* __restrict__ W1,
                const float* __restrict__ b1,
                const float* __restrict__ W2,
                const float* __restrict__ b2,
                float* __restrict__ out)
{
    // x staging: [neighbor][row(batch)][k] fp16, k padded 6->8
    __shared__ __half xs[NBR][TILE_B][8];
    // W1 transposed: [n][k8] fp16
    __shared__ __half w1t[HID][8];
    // A-fragment exchange, double buffered: [buf][k-chunk][lane] 16B
    // chunk c (k cols 16c..16c+16) is produced by warp c, consumed by all.
    __shared__ uint4 exch[2][16][32];

    const int tid  = threadIdx.x;
    const int w    = tid >> 5;      // warp id = 16-col hidden/output n-slice
    const int lane = tid & 31;
    const int gid  = lane >> 2;     // fragment row group (0..7)
    const int tig  = lane & 3;      // thread-in-group
    const int n0   = w * 16;

    // ---- stage W1^T into smem (zero-pad k=6,7) ----
    for (int i = tid; i < HID * 8; i += THREADS) {
        int n = i >> 3, k = i & 7;
        w1t[n][k] = (k < 6) ? __float2half(W1[k * HID + n]) : __float2half(0.0f);
    }

    // ---- per-thread bias fragments (2 n8-tiles per warp) ----
    float2 b1v[2], b2v[2];
    #pragma unroll
    for (int j = 0; j < 2; j++) {
        int c = n0 + j * 8 + 2 * tig;   // layer-1 tiles and layer-2 tiles cover same cols
        b1v[j] = make_float2(b1[c], b1[c + 1]);
        b2v[j] = make_float2(b2[c], b2[c + 1]);
    }

    // ---- resident W2 B-fragments: warp w holds W2[:, n0..n0+15] ----
    uint32_t blo[16][2], bhi[16][2];
    #pragma unroll
    for (int c = 0; c < 16; c++) {
        #pragma unroll
        for (int t = 0; t < 2; t++) {
            int n = n0 + t * 8 + gid;
            int k = c * 16 + 2 * tig;
            blo[c][t] = packh2(W2[k * HID + n],       W2[(k + 1) * HID + n]);
            bhi[c][t] = packh2(W2[(k + 8) * HID + n], W2[(k + 9) * HID + n]);
        }
    }
    __syncthreads();   // w1t ready

    const float inv6 = 1.0f / 6.0f;

    for (int tile = blockIdx.x; tile < NTILES; tile += gridDim.x) {
        // ---- stage x (neighbor obs) for 16 batches ----
        for (int i = tid; i < NBR * TILE_B * 6; i += THREADS) {
            int k  = i % 6;
            int r  = (i / 6) % TILE_B;
            int nb = i / (6 * TILE_B);
            long b = (long)tile * TILE_B + r;
            xs[nb][r][k] = __float2half(obs[b * OBS_STRIDE + SELF_OBS + nb * 6 + k]);
        }
        if (tid < NBR * TILE_B) {   // zero pad k = 6,7
            *reinterpret_cast<uint32_t*>(&xs[tid / TILE_B][tid % TILE_B][6]) = 0u;
        }
        __syncthreads();

        float acc[2][4];
        #pragma unroll
        for (int t = 0; t < 2; t++)
            #pragma unroll
            for (int i = 0; i < 4; i++) acc[t][i] = 0.0f;

        #pragma unroll 1
        for (int nb = 0; nb < NBR; nb++) {
            const int buf = nb & 1;

            // ---- layer 1: warp w computes h1[16 rows x cols 16w..16w+16] -> A-frag of chunk w ----
            {
                uint32_t xa0 = *reinterpret_cast<const uint32_t*>(&xs[nb][gid][2 * tig]);
                uint32_t xa1 = *reinterpret_cast<const uint32_t*>(&xs[nb][gid + 8][2 * tig]);
                uint4 pk;
                uint32_t* pkr = reinterpret_cast<uint32_t*>(&pk);
                #pragma unroll
                for (int j = 0; j < 2; j++) {
                    int tt = 2 * w + j;            // global hidden n8-tile
                    uint32_t bb = *reinterpret_cast<const uint32_t*>(&w1t[tt * 8 + gid][2 * tig]);
                    float d0 = 0.f, d1 = 0.f, d2 = 0.f, d3 = 0.f;
                    mma_k8(d0, d1, d2, d3, xa0, xa1, bb);
                    d0 += b1v[j].x; d1 += b1v[j].y;
                    d2 += b1v[j].x; d3 += b1v[j].y;
                    // j=0 -> klo halves (a0: row gid, a1: row gid+8); j=1 -> khi (a2, a3)
                    pkr[j * 2 + 0] = packh2(tanha(d0), tanha(d1));
                    pkr[j * 2 + 1] = packh2(tanha(d2), tanha(d3));
                }
                exch[buf][w][lane] = pk;
            }
            __syncthreads();   // all A-fragments of this neighbor visible

            // ---- layer 2: D[16 x 16] = h1[16 x 256] @ W2[:, n0..n0+15] ----
            float D[2][4];
            #pragma unroll
            for (int t = 0; t < 2; t++)
                #pragma unroll
                for (int i = 0; i < 4; i++) D[t][i] = 0.0f;

            #pragma unroll
            for (int c = 0; c < 16; c++) {
                uint4 a = exch[buf][c][lane];
                #pragma unroll
                for (int t = 0; t < 2; t++)
                    mma_k16(D[t], a.x, a.y, a.z, a.w, blo[c][t], bhi[c][t]);
            }

            // ---- epilogue: acc += tanh(D + b2) ----
            #pragma unroll
            for (int t = 0; t < 2; t++) {
                acc[t][0] += tanha(D[t][0] + b2v[t].x);
                acc[t][1] += tanha(D[t][1] + b2v[t].y);
                acc[t][2] += tanha(D[t][2] + b2v[t].x);
                acc[t][3] += tanha(D[t][3] + b2v[t].y);
            }
            // no second barrier: next iteration writes the other exch buffer, and
            // the barrier above separates read(nb-1) from write(nb+1) of the same buffer.
        }

        // ---- mean over neighbors, write out ----
        long b = (long)tile * TILE_B;
        #pragma unroll
        for (int t = 0; t < 2; t++) {
            int col = n0 + t * 8 + 2 * tig;
            float2 v0 = make_float2(acc[t][0] * inv6, acc[t][1] * inv6);
            float2 v1 = make_float2(acc[t][2] * inv6, acc[t][3] * inv6);
            *reinterpret_cast<float2*>(&out[(b + gid)     * HID + col]) = v0;
            *reinterpret_cast<float2*>(&out[(b + gid + 8) * HID + col]) = v1;
        }
        __syncthreads();   // protect xs / last exch buffer before next tile's staging
    }
}

// ==================== launch ====================
extern "C" void kernel_launch(void* const* d_in, const int* in_sizes, int n_in,
                              void* d_out, int out_size) {
    // inputs: self_obs(131072*18), obs(131072*54), W1(6*256), b1(256), W2(256*256), b2(256)
    const float* obs = nullptr;
    const float* W1  = nullptr;
    const float* b1  = nullptr;
    const float* W2  = nullptr;
    const float* b2  = nullptr;
    for (int i = 0; i < n_in; i++) {
        int sz = in_sizes[i];
        if (sz == BATCH_N * OBS_STRIDE)  obs = (const float*)d_in[i];
        else if (sz == 6 * HID)          W1  = (const float*)d_in[i];
        else if (sz == HID * HID)        W2  = (const float*)d_in[i];
        else if (sz == HID) {
            if (!b1) b1 = (const float*)d_in[i];
            else if (!b2) b2 = (const float*)d_in[i];
        }
    }
    float* out = (float*)d_out;
    deepsets_kernel<<<GRID_X, THREADS>>>(obs, W1, b1, W2, b2, out);
}

// round 7
// speedup vs baseline: 1.1115x; 1.0289x over previous
#include <cuda_runtime.h>
#include <cuda_fp16.h>
#include <cstdint>

// ---------------- problem constants ----------------
#define HID        256
#define OBS_STRIDE 54
#define SELF_OBS   18
#define NBR        6
#define BATCH_N    131072
#define TILE_B     16                    // batches per CTA iteration
#define NTILES     (BATCH_N / TILE_B)    // 8192
#define THREADS    512                   // 16 warps: warp w owns hidden/output cols [16w, 16w+16)
#define GRID_X     152
#define SMEM_BYTES (NBR * 16 * 32 * 16)  // exch[6][16][32] uint4 = 49152

// ==================== helpers ====================
static __device__ __forceinline__ float tanha(float x) {
    float y;
    asm("tanh.approx.f32 %0, %1;" : "=f"(y) : "f"(x));
    return y;
}
static __device__ __forceinline__ uint32_t packh2(float a, float b) {
    __half2 h = __floats2half2_rn(a, b);
    return *reinterpret_cast<uint32_t*>(&h);
}
// D[16x8] += A[16x8] * B[8x8]   (f16 in, f32 accum)
static __device__ __forceinline__ void mma_k8(float& d0, float& d1, float& d2, float& d3,
                                              uint32_t a0, uint32_t a1, uint32_t b0) {
    asm volatile("mma.sync.aligned.m16n8k8.row.col.f32.f16.f16.f32 "
                 "{%0,%1,%2,%3}, {%4,%5}, {%6}, {%0,%1,%2,%3};"
                 : "+f"(d0), "+f"(d1), "+f"(d2), "+f"(d3)
                 : "r"(a0), "r"(a1), "r"(b0));
}
// D[16x8] += A[16x16] * B[16x8]
static __device__ __forceinline__ void mma_k16(float* d,
                                               uint32_t a0, uint32_t a1, uint32_t a2, uint32_t a3,
                                               uint32_t b0, uint32_t b1) {
    asm volatile("mma.sync.aligned.m16n8k16.row.col.f32.f16.f16.f32 "
                 "{%0,%1,%2,%3}, {%4,%5,%6,%7}, {%8,%9}, {%0,%1,%2,%3};"
                 : "+f"(d[0]), "+f"(d[1]), "+f"(d[2]), "+f"(d[3])
                 : "r"(a0), "r"(a1), "r"(a2), "r"(a3), "r"(b0), "r"(b1));
}

// ==================== kernel ====================
__global__ void __launch_bounds__(THREADS, 1)
deepsets_kernel(const float* __restrict__ obs,
                const float* __restrict__ W1,
                const float* __restrict__ b1,
                const float* __restrict__ W2,
                const float* __restrict__ b2,
                float* __restrict__ out)
{
    // A-fragment exchange for ALL 6 neighbors of the current tile:
    // exch[nb][k-chunk][lane], chunk c produced by warp c, consumed by all warps.
    extern __shared__ uint4 exch[];

    const int tid  = threadIdx.x;
    const int w    = tid >> 5;      // warp id = 16-col hidden/output n-slice
    const int lane = tid & 31;
    const int gid  = lane >> 2;     // fragment row group (0..7)
    const int tig  = lane & 3;      // thread-in-group
    const int n0   = w * 16;

    // ---- resident W1 B-fragments (2 regs) + bias fragments ----
    uint32_t w1b[2];
    float2 b1v[2], b2v[2];
    #pragma unroll
    for (int j = 0; j < 2; j++) {
        int tt = 2 * w + j;                 // global hidden n8-tile
        int n  = tt * 8 + gid;
        int c  = tt * 8 + 2 * tig;
        w1b[j] = (tig < 3) ? packh2(W1[2 * tig * HID + n], W1[(2 * tig + 1) * HID + n]) : 0u;
        b1v[j] = make_float2(b1[c], b1[c + 1]);
        b2v[j] = make_float2(b2[c], b2[c + 1]);
    }

    // ---- resident W2 B-fragments: warp w holds W2[:, n0..n0+15] (64 regs) ----
    uint32_t blo[16][2], bhi[16][2];
    #pragma unroll
    for (int c = 0; c < 16; c++) {
        #pragma unroll
        for (int t = 0; t < 2; t++) {
            int n = n0 + t * 8 + gid;
            int k = c * 16 + 2 * tig;
            blo[c][t] = packh2(W2[k * HID + n],       W2[(k + 1) * HID + n]);
            bhi[c][t] = packh2(W2[(k + 8) * HID + n], W2[(k + 9) * HID + n]);
        }
    }

    const float inv6 = 1.0f / 6.0f;

    for (int tile = blockIdx.x; tile < NTILES; tile += gridDim.x) {
        const long b0 = (long)tile * TILE_B;

        // ======== phase A: layer 1 for all 6 neighbors (one MUFU burst) ========
        // warp w produces h1[16 rows x cols 16w..16w+16] -> A-frag chunk w, per neighbor.
        #pragma unroll
        for (int nb = 0; nb < NBR; nb++) {
            uint32_t xa0 = 0u, xa1 = 0u;
            if (tig < 3) {   // k = 2*tig, 2*tig+1 < 6 ; tig==3 is the zero pad
                const float* p = obs + (b0 + gid) * OBS_STRIDE + SELF_OBS + nb * 6 + 2 * tig;
                float2 v0 = *reinterpret_cast<const float2*>(p);
                float2 v1 = *reinterpret_cast<const float2*>(p + 8 * OBS_STRIDE);
                xa0 = packh2(v0.x, v0.y);
                xa1 = packh2(v1.x, v1.y);
            }
            uint4 pk;
            uint32_t* pkr = reinterpret_cast<uint32_t*>(&pk);
            #pragma unroll
            for (int j = 0; j < 2; j++) {
                float d0 = 0.f, d1 = 0.f, d2 = 0.f, d3 = 0.f;
                mma_k8(d0, d1, d2, d3, xa0, xa1, w1b[j]);
                // j=0 -> k-lo halves (row gid, row gid+8); j=1 -> k-hi
                pkr[j * 2 + 0] = packh2(tanha(d0 + b1v[j].x), tanha(d1 + b1v[j].y));
                pkr[j * 2 + 1] = packh2(tanha(d2 + b1v[j].x), tanha(d3 + b1v[j].y));
            }
            exch[(nb * 16 + w) * 32 + lane] = pk;
        }
        __syncthreads();   // all A-fragments of all 6 neighbors visible

        // ======== phase B: 6 MMA bursts, epilogue of nb deferred into nb+1 ========
        float acc[2][4];
        #pragma unroll
        for (int t = 0; t < 2; t++)
            #pragma unroll
            for (int i = 0; i < 4; i++) acc[t][i] = 0.0f;

        float Dp[2][4];
        #pragma unroll
        for (int nb = 0; nb < NBR; nb++) {
            float D[2][4];
            #pragma unroll
            for (int t = 0; t < 2; t++)
                #pragma unroll
                for (int i = 0; i < 4; i++) D[t][i] = 0.0f;

            #pragma unroll
            for (int c = 0; c < 16; c++) {
                uint4 a = exch[(nb * 16 + c) * 32 + lane];
                mma_k16(D[0], a.x, a.y, a.z, a.w, blo[c][0], bhi[c][0]);
                mma_k16(D[1], a.x, a.y, a.z, a.w, blo[c][1], bhi[c][1]);
            }

            // deferred epilogue of previous neighbor: independent of this burst's
            // HMMAs -> ptxas interleaves the MUFUs under the tensor issue slots.
            if (nb > 0) {
                #pragma unroll
                for (int t = 0; t < 2; t++) {
                    acc[t][0] += tanha(Dp[t][0] + b2v[t].x);
                    acc[t][1] += tanha(Dp[t][1] + b2v[t].y);
                    acc[t][2] += tanha(Dp[t][2] + b2v[t].x);
                    acc[t][3] += tanha(Dp[t][3] + b2v[t].y);
                }
            }
            #pragma unroll
            for (int t = 0; t < 2; t++)
                #pragma unroll
                for (int i = 0; i < 4; i++) Dp[t][i] = D[t][i];   // register rename
        }
        // last neighbor's epilogue
        #pragma unroll
        for (int t = 0; t < 2; t++) {
            acc[t][0] += tanha(Dp[t][0] + b2v[t].x);
            acc[t][1] += tanha(Dp[t][1] + b2v[t].y);
            acc[t][2] += tanha(Dp[t][2] + b2v[t].x);
            acc[t][3] += tanha(Dp[t][3] + b2v[t].y);
        }

        // ---- mean over neighbors, write out ----
        #pragma unroll
        for (int t = 0; t < 2; t++) {
            int col = n0 + t * 8 + 2 * tig;
            float2 v0 = make_float2(acc[t][0] * inv6, acc[t][1] * inv6);
            float2 v1 = make_float2(acc[t][2] * inv6, acc[t][3] * inv6);
            *reinterpret_cast<float2*>(&out[(b0 + gid)     * HID + col]) = v0;
            *reinterpret_cast<float2*>(&out[(b0 + gid + 8) * HID + col]) = v1;
        }
        __syncthreads();   // protect exch reads before next tile's phase A writes
    }
}

// ==================== launch ====================
extern "C" void kernel_launch(void* const* d_in, const int* in_sizes, int n_in,
                              void* d_out, int out_size) {
    // inputs: self_obs(131072*18), obs(131072*54), W1(6*256), b1(256), W2(256*256), b2(256)
    const float* obs = nullptr;
    const float* W1  = nullptr;
    const float* b1  = nullptr;
    const float* W2  = nullptr;
    const float* b2  = nullptr;
    for (int i = 0; i < n_in; i++) {
        int sz = in_sizes[i];
        if (sz == BATCH_N * OBS_STRIDE)  obs = (const float*)d_in[i];
        else if (sz == 6 * HID)          W1  = (const float*)d_in[i];
        else if (sz == HID * HID)        W2  = (const float*)d_in[i];
        else if (sz == HID) {
            if (!b1) b1 = (const float*)d_in[i];
            else if (!b2) b2 = (const float*)d_in[i];
        }
    }
    float* out = (float*)d_out;

    cudaFuncSetAttribute(deepsets_kernel,
                         cudaFuncAttributeMaxDynamicSharedMemorySize, SMEM_BYTES);
    deepsets_kernel<<<GRID_X, THREADS, SMEM_BYTES>>>(obs, W1, b1, W2, b2, out);
}